// round 11
// baseline (speedup 1.0000x reference)
#include <cuda_runtime.h>
#include <math.h>
#include <stdint.h>

#define B_   64
#define S_   512
#define H_   1024
#define BH_  (B_ * H_)          // 65536
#define NCTA 128                // persistent-kernel grid (must be <= #SMs)
#define KSPL 8                  // k-split slices (128 k each)
#define JTIL 16                 // j tiles of 64

// ---------------- device scratch (no allocations allowed) ----------------
__device__ float    g_xi[(size_t)S_ * B_ * H_];   // 128 MB, time-major (s,b,h)
__device__ float    g_part[KSPL * BH_];           // 2 MB partial pre-activations
__device__ unsigned g_bar;                        // grid barrier counter

__global__ void init_bar_kernel() { g_bar = 0u; }

// =========================================================================
// Kernel 1: xi[s][b][j] = dot(x[b][s][:], W_ih[j][:]) + b_ih[j]
// 128x128 tile, K-chunks of 16, 256 threads, 8x8 microtile.
// Output row r = s*64 + b  (time-major), so tile rt covers s = 2*rt, 2*rt+1.
// =========================================================================
__global__ __launch_bounds__(256, 2) void gemm_xi_kernel(
    const float* __restrict__ x,
    const float* __restrict__ Wih,
    const float* __restrict__ bih)
{
    __shared__ float As[16 * 132];   // transposed: As[k][row]
    __shared__ float Bs[16 * 132];   // transposed: Bs[k][j]

    const int t  = threadIdx.x;
    const int jt = blockIdx.x;       // 0..7   (128 j each)
    const int rt = blockIdx.y;       // 0..255 (128 rows each)
    const int tr = t >> 4;           // 0..15
    const int tc = t & 15;           // 0..15
    const int r0 = rt * 128;
    const int j0 = jt * 128;

    float acc[8][8];
#pragma unroll
    for (int i = 0; i < 8; i++)
#pragma unroll
        for (int j = 0; j < 8; j++) acc[i][j] = 0.f;

    for (int k0 = 0; k0 < H_; k0 += 16) {
        // ---- stage A (128 rows x 16 k) and B (128 j x 16 k), transposed ----
#pragma unroll
        for (int i = 0; i < 2; i++) {
            const int f   = t + 256 * i;      // 0..511 float4 slots
            const int row = f >> 2;           // 0..127
            const int k4  = f & 3;            // 0..3
            const int r   = r0 + row;
            const int b   = r & 63;
            const int s   = r >> 6;
            const float4 va = *(const float4*)(x + ((size_t)(b * S_ + s)) * H_ + (k0 + k4 * 4));
            As[(k4 * 4 + 0) * 132 + row] = va.x;
            As[(k4 * 4 + 1) * 132 + row] = va.y;
            As[(k4 * 4 + 2) * 132 + row] = va.z;
            As[(k4 * 4 + 3) * 132 + row] = va.w;
            const float4 vb = *(const float4*)(Wih + ((size_t)(j0 + row)) * H_ + (k0 + k4 * 4));
            Bs[(k4 * 4 + 0) * 132 + row] = vb.x;
            Bs[(k4 * 4 + 1) * 132 + row] = vb.y;
            Bs[(k4 * 4 + 2) * 132 + row] = vb.z;
            Bs[(k4 * 4 + 3) * 132 + row] = vb.w;
        }
        __syncthreads();

        // ---- compute ----
#pragma unroll
        for (int kk = 0; kk < 16; kk++) {
            float a[8], w[8];
            const float4 a0 = *(const float4*)&As[kk * 132 + tr * 8];
            const float4 a1 = *(const float4*)&As[kk * 132 + tr * 8 + 4];
            const float4 w0 = *(const float4*)&Bs[kk * 132 + tc * 8];
            const float4 w1 = *(const float4*)&Bs[kk * 132 + tc * 8 + 4];
            a[0]=a0.x; a[1]=a0.y; a[2]=a0.z; a[3]=a0.w;
            a[4]=a1.x; a[5]=a1.y; a[6]=a1.z; a[7]=a1.w;
            w[0]=w0.x; w[1]=w0.y; w[2]=w0.z; w[3]=w0.w;
            w[4]=w1.x; w[5]=w1.y; w[6]=w1.z; w[7]=w1.w;
#pragma unroll
            for (int ii = 0; ii < 8; ii++)
#pragma unroll
                for (int jj = 0; jj < 8; jj++)
                    acc[ii][jj] = fmaf(a[ii], w[jj], acc[ii][jj]);
        }
        __syncthreads();
    }

    // ---- epilogue: add bias, write xi time-major ----
    float bias[8];
#pragma unroll
    for (int jj = 0; jj < 8; jj++) bias[jj] = bih[j0 + tc * 8 + jj];
#pragma unroll
    for (int ii = 0; ii < 8; ii++) {
        const int r = r0 + tr * 8 + ii;
        float* o = g_xi + (size_t)r * H_ + j0 + tc * 8;
        float4 v0, v1;
        v0.x = acc[ii][0] + bias[0]; v0.y = acc[ii][1] + bias[1];
        v0.z = acc[ii][2] + bias[2]; v0.w = acc[ii][3] + bias[3];
        v1.x = acc[ii][4] + bias[4]; v1.y = acc[ii][5] + bias[5];
        v1.z = acc[ii][6] + bias[6]; v1.w = acc[ii][7] + bias[7];
        *(float4*)(o)     = v0;
        *(float4*)(o + 4) = v1;
    }
}

// =========================================================================
// Persistent recurrence kernel: 128 CTAs, software grid barrier.
// CTA = (jt, ks): j in [jt*64, jt*64+64), k in [ks*128, ks*128+128).
// W_hh slice is SMEM-resident for the whole sequence.
// =========================================================================
__device__ __forceinline__ void grid_bar(unsigned& target)
{
    target += NCTA;
    __syncthreads();
    if (threadIdx.x == 0) {
        __threadfence();                       // release prior writes
        atomicAdd(&g_bar, 1u);
        while (*(volatile unsigned*)&g_bar < target) { }
        __threadfence();                       // acquire others' writes
    }
    __syncthreads();
}

__global__ __launch_bounds__(256, 1) void rnn_kernel(
    const float* __restrict__ Whh,
    const float* __restrict__ bhh,
    float* __restrict__ out)                   // d_out: (S,B,H) then h_final
{
    extern __shared__ float sm[];
    float* Ws = sm;                  // [128][68]  (k-local, j-local)
    float* Hs = sm + 128 * 68;       // [128][68]  (k-local, b)

    const int t   = threadIdx.x;
    const int cta = blockIdx.x;
    const int jt  = cta >> 3;        // 0..15
    const int ks  = cta & 7;         // 0..7
    const int tr  = t >> 4;          // 0..15
    const int tc  = t & 15;          // 0..15
    const int b0  = tr * 4;
    const int j0l = tc * 4;

    // ---- load W_hh slice once (resident for all 512 steps) ----
#pragma unroll 4
    for (int i = 0; i < 32; i++) {
        const int f  = t + 256 * i;          // 0..8191
        const int kk = f & 127;
        const int j  = f >> 7;               // 0..63
        Ws[kk * 68 + j] = Whh[(size_t)(jt * 64 + j) * H_ + ks * 128 + kk];
    }

    unsigned target = 0;

    for (int s = 0; s < S_; s++) {
        // ---- phase 1a: stage h_prev slice (k-major) ----
        if (s == 0) {
#pragma unroll 4
            for (int i = 0; i < 32; i++) {
                const int f = t + 256 * i;
                Hs[(f & 127) * 68 + (f >> 7)] = 0.f;
            }
        } else {
            const float* hp = out + (size_t)(s - 1) * BH_;
#pragma unroll 4
            for (int i = 0; i < 32; i++) {
                const int f  = t + 256 * i;
                const int kk = f & 127;
                const int b  = f >> 7;
                Hs[kk * 68 + b] = hp[b * H_ + ks * 128 + kk];
            }
        }
        __syncthreads();

        // ---- phase 1b: 64x64x128 partial GEMM, 4x4 microtile ----
        float acc[4][4];
#pragma unroll
        for (int i = 0; i < 4; i++)
#pragma unroll
            for (int j = 0; j < 4; j++) acc[i][j] = 0.f;

#pragma unroll 8
        for (int kk = 0; kk < 128; kk++) {
            const float4 hv = *(const float4*)&Hs[kk * 68 + b0];
            const float4 wv = *(const float4*)&Ws[kk * 68 + j0l];
            const float hb[4] = {hv.x, hv.y, hv.z, hv.w};
            const float wb[4] = {wv.x, wv.y, wv.z, wv.w};
#pragma unroll
            for (int ii = 0; ii < 4; ii++)
#pragma unroll
                for (int jj = 0; jj < 4; jj++)
                    acc[ii][jj] = fmaf(hb[ii], wb[jj], acc[ii][jj]);
        }

        // ---- write partials: g_part[ks][b][j_global] ----
#pragma unroll
        for (int ii = 0; ii < 4; ii++) {
            float4 v;
            v.x = acc[ii][0]; v.y = acc[ii][1]; v.z = acc[ii][2]; v.w = acc[ii][3];
            *(float4*)&g_part[(size_t)(ks * 64 + b0 + ii) * H_ + jt * 64 + j0l] = v;
        }

        grid_bar(target);   // all partials visible

        // ---- phase 2: reduce + bias + xi + tanh, write output slice ----
        {
            const int base = cta * 512;
#pragma unroll
            for (int i = 0; i < 2; i++) {
                const int idx = base + t + 256 * i;      // 0..65535
                const int hh  = idx & (H_ - 1);
                float v = g_xi[(size_t)s * BH_ + idx] + bhh[hh];
#pragma unroll
                for (int q = 0; q < KSPL; q++) v += g_part[q * BH_ + idx];
                const float hval = tanhf(v);
                out[(size_t)s * BH_ + idx] = hval;
                if (s == S_ - 1)
                    out[(size_t)S_ * BH_ + idx] = hval;   // h_final tail
            }
        }

        grid_bar(target);   // h_t visible before next step's staging
    }
}

// =========================================================================
extern "C" void kernel_launch(void* const* d_in, const int* in_sizes, int n_in,
                              void* d_out, int out_size)
{
    (void)in_sizes; (void)n_in; (void)out_size;
    const float* x   = (const float*)d_in[0];
    const float* Wih = (const float*)d_in[1];
    const float* bih = (const float*)d_in[2];
    const float* Whh = (const float*)d_in[3];
    const float* bhh = (const float*)d_in[4];
    float* out = (float*)d_out;

    const int rnn_smem = 2 * 128 * 68 * (int)sizeof(float);   // 69632 B
    cudaFuncSetAttribute(rnn_kernel, cudaFuncAttributeMaxDynamicSharedMemorySize, rnn_smem);

    init_bar_kernel<<<1, 1>>>();
    gemm_xi_kernel<<<dim3(8, 256, 1), 256>>>(x, Wih, bih);
    rnn_kernel<<<NCTA, 256, rnn_smem>>>(Whh, bhh, out);
}

// round 13
// speedup vs baseline: 1.1568x; 1.1568x over previous
#include <cuda_runtime.h>
#include <cuda_bf16.h>
#include <math.h>
#include <stdint.h>

#define B_   64
#define S_   512
#define H_   1024
#define BH_  (B_ * H_)          // 65536
#define NCTA 128                // persistent-kernel grid (must be <= #SMs)
#define KSPL 8                  // k-split slices (128 k each)

// ---------------- device scratch (no allocations allowed) ----------------
__device__ float    g_xi[(size_t)S_ * B_ * H_];   // 128 MB, time-major (s,b,h)
__device__ float    g_part[KSPL * BH_];           // 2 MB partial pre-activations
__device__ unsigned g_bar;                        // grid barrier counter

__global__ void init_bar_kernel() { g_bar = 0u; }

// ======================= helpers =======================
__device__ __forceinline__ uint32_t smem_u32(const void* p) {
    uint32_t a;
    asm("{ .reg .u64 t; cvta.to.shared.u64 t, %1; cvt.u32.u64 %0, t; }" : "=r"(a) : "l"(p));
    return a;
}

// fp32x4 -> (bf16 hi x4, bf16 lo x4), each packed as uint2 (mem order .x=lo pair)
__device__ __forceinline__ void cvt_split4(float4 v, uint2& hi, uint2& lo) {
    uint32_t h0, h1, l0, l1;
    asm("cvt.rn.satfinite.bf16x2.f32 %0, %1, %2;" : "=r"(h0) : "f"(v.y), "f"(v.x));
    asm("cvt.rn.satfinite.bf16x2.f32 %0, %1, %2;" : "=r"(h1) : "f"(v.w), "f"(v.z));
    float r0 = v.x - __uint_as_float(h0 << 16);
    float r1 = v.y - __uint_as_float(h0 & 0xFFFF0000u);
    float r2 = v.z - __uint_as_float(h1 << 16);
    float r3 = v.w - __uint_as_float(h1 & 0xFFFF0000u);
    asm("cvt.rn.satfinite.bf16x2.f32 %0, %1, %2;" : "=r"(l0) : "f"(r1), "f"(r0));
    asm("cvt.rn.satfinite.bf16x2.f32 %0, %1, %2;" : "=r"(l1) : "f"(r3), "f"(r2));
    hi = make_uint2(h0, h1);
    lo = make_uint2(l0, l1);
}

#define LDMX4(r0, r1, r2, r3, addr) \
    asm volatile("ldmatrix.sync.aligned.m8n8.x4.shared.b16 {%0,%1,%2,%3}, [%4];" \
        : "=r"(r0), "=r"(r1), "=r"(r2), "=r"(r3) : "r"(addr))

#define MMA_BF16(c, a0, a1, a2, a3, b0, b1) \
    asm volatile("mma.sync.aligned.m16n8k16.row.col.f32.bf16.bf16.f32 " \
        "{%0,%1,%2,%3}, {%4,%5,%6,%7}, {%8,%9}, {%0,%1,%2,%3};" \
        : "+f"((c)[0]), "+f"((c)[1]), "+f"((c)[2]), "+f"((c)[3]) \
        : "r"(a0), "r"(a1), "r"(a2), "r"(a3), "r"(b0), "r"(b1))

// =========================================================================
// Kernel 1 (HMMA): xi[r][j] = dot(x_row(r), W_ih[j]) + b_ih[j]
// r = s*64+b time-major. Grid (8 jt, 256 rt). CTA tile 128x128, K-chunk 64.
// bf16 hi/lo split: C = Ahi*Whi + Ahi*Wlo + Alo*Whi, fp32 accumulation.
// 8 warps (2 M x 4 N), warp tile 64x32, mma m16n8k16.
// =========================================================================
#define KC        64
#define LDSTR     72                         // bf16 elems per SMEM row (pad 8)
#define TILE_ELM  (128 * LDSTR)              // 9216 bf16 per tile
#define GEMM_SMEM (4 * TILE_ELM * 2)         // 73728 bytes

__global__ __launch_bounds__(256, 2) void gemm_xi_mma(
    const float* __restrict__ x,
    const float* __restrict__ Wih,
    const float* __restrict__ bih)
{
    extern __shared__ __nv_bfloat16 smb[];
    __nv_bfloat16* As_hi = smb;
    __nv_bfloat16* As_lo = smb + TILE_ELM;
    __nv_bfloat16* Bs_hi = smb + 2 * TILE_ELM;
    __nv_bfloat16* Bs_lo = smb + 3 * TILE_ELM;

    const uint32_t ahi = smem_u32(As_hi);
    const uint32_t alo = smem_u32(As_lo);
    const uint32_t bhi = smem_u32(Bs_hi);
    const uint32_t blo = smem_u32(Bs_lo);

    const int t      = threadIdx.x;
    const int lane   = t & 31;
    const int wid    = t >> 5;
    const int warp_m = wid >> 2;             // 0..1
    const int warp_n = wid & 3;              // 0..3
    const int jt = blockIdx.x;               // 0..7
    const int rt = blockIdx.y;               // 0..255
    const int r0 = rt * 128;
    const int j0 = jt * 128;

    float acc[4][4][4];
#pragma unroll
    for (int mi = 0; mi < 4; mi++)
#pragma unroll
        for (int ni = 0; ni < 4; ni++)
#pragma unroll
            for (int q = 0; q < 4; q++) acc[mi][ni][q] = 0.f;

    // ldmatrix lane address components (element offsets within a tile)
    const int a_row = lane & 15;             // + m0
    const int a_kof = ((lane >> 4) & 1) * 8; // + kk
    const int b_row = (lane & 7) + ((lane >> 4) & 1) * 8;  // + n0
    const int b_kof = ((lane >> 3) & 1) * 8;               // + kk

    for (int kb = 0; kb < 16; kb++) {
        const int k0 = kb * KC;
        // ---- stage: fp32 -> bf16 hi/lo split into padded SMEM ----
#pragma unroll
        for (int i = 0; i < 8; i++) {
            const int f   = t + 256 * i;     // float4 slot 0..2047
            const int row = f >> 4;          // 0..127
            const int k4  = (f & 15) << 2;   // 0..60
            const int eo  = row * LDSTR + k4;
            uint2 h, l;
            const int r = r0 + row;
            const float4 va = *(const float4*)(
                x + ((size_t)((r & 63) * S_ + (r >> 6))) * H_ + k0 + k4);
            cvt_split4(va, h, l);
            *(uint2*)(As_hi + eo) = h;
            *(uint2*)(As_lo + eo) = l;
            const float4 vw = *(const float4*)(
                Wih + ((size_t)(j0 + row)) * H_ + k0 + k4);
            cvt_split4(vw, h, l);
            *(uint2*)(Bs_hi + eo) = h;
            *(uint2*)(Bs_lo + eo) = l;
        }
        __syncthreads();

        // ---- compute: 4 k16 steps ----
#pragma unroll
        for (int kk = 0; kk < KC; kk += 16) {
            // B fragments: 4 n8 frags for hi and lo (2 x4 loads each)
            uint32_t bh[8], bl[8];
#pragma unroll
            for (int p = 0; p < 2; p++) {
                const int n0 = warp_n * 32 + p * 16;
                const uint32_t off = (uint32_t)(((n0 + b_row) * LDSTR + kk + b_kof) * 2);
                LDMX4(bh[p*4+0], bh[p*4+1], bh[p*4+2], bh[p*4+3], bhi + off);
                LDMX4(bl[p*4+0], bl[p*4+1], bl[p*4+2], bl[p*4+3], blo + off);
            }
#pragma unroll
            for (int mi = 0; mi < 4; mi++) {
                const int m0 = warp_m * 64 + mi * 16;
                const uint32_t off = (uint32_t)(((m0 + a_row) * LDSTR + kk + a_kof) * 2);
                uint32_t ah0, ah1, ah2, ah3, al0, al1, al2, al3;
                LDMX4(ah0, ah1, ah2, ah3, ahi + off);
                LDMX4(al0, al1, al2, al3, alo + off);
#pragma unroll
                for (int ni = 0; ni < 4; ni++) {
                    const uint32_t b0h = bh[ni*2+0], b1h = bh[ni*2+1];
                    const uint32_t b0l = bl[ni*2+0], b1l = bl[ni*2+1];
                    MMA_BF16(acc[mi][ni], ah0, ah1, ah2, ah3, b0h, b1h);
                    MMA_BF16(acc[mi][ni], ah0, ah1, ah2, ah3, b0l, b1l);
                    MMA_BF16(acc[mi][ni], al0, al1, al2, al3, b0h, b1h);
                }
            }
        }
        __syncthreads();
    }

    // ---- epilogue: + bias, write g_xi (time-major rows) ----
    const int gr = lane >> 2;                // 0..7
    const int gc = (lane & 3) * 2;           // even col
#pragma unroll
    for (int ni = 0; ni < 4; ni++) {
        const int col = j0 + warp_n * 32 + ni * 8 + gc;
        const float bia0 = __ldg(bih + col);
        const float bia1 = __ldg(bih + col + 1);
#pragma unroll
        for (int mi = 0; mi < 4; mi++) {
            const int row = r0 + warp_m * 64 + mi * 16 + gr;
            float2 v0, v1;
            v0.x = acc[mi][ni][0] + bia0;
            v0.y = acc[mi][ni][1] + bia1;
            v1.x = acc[mi][ni][2] + bia0;
            v1.y = acc[mi][ni][3] + bia1;
            *(float2*)(g_xi + (size_t)row * H_ + col)       = v0;
            *(float2*)(g_xi + (size_t)(row + 8) * H_ + col) = v1;
        }
    }
}

// =========================================================================
// Persistent recurrence kernel (UNCHANGED from R11 — proven correct):
// 128 CTAs, software grid barrier. CTA = (jt, ks).
// =========================================================================
__device__ __forceinline__ void grid_bar(unsigned& target)
{
    target += NCTA;
    __syncthreads();
    if (threadIdx.x == 0) {
        __threadfence();                       // release prior writes
        atomicAdd(&g_bar, 1u);
        while (*(volatile unsigned*)&g_bar < target) { }
        __threadfence();                       // acquire others' writes
    }
    __syncthreads();
}

__global__ __launch_bounds__(256, 1) void rnn_kernel(
    const float* __restrict__ Whh,
    const float* __restrict__ bhh,
    float* __restrict__ out)                   // d_out: (S,B,H) then h_final
{
    extern __shared__ float smf[];
    float* Ws = smf;                 // [128][68]  (k-local, j-local)
    float* Hs = smf + 128 * 68;      // [128][68]  (k-local, b)

    const int t   = threadIdx.x;
    const int cta = blockIdx.x;
    const int jt  = cta >> 3;        // 0..15
    const int ks  = cta & 7;         // 0..7
    const int tr  = t >> 4;          // 0..15
    const int tc  = t & 15;          // 0..15
    const int b0  = tr * 4;
    const int j0l = tc * 4;

    // ---- load W_hh slice once (resident for all 512 steps) ----
#pragma unroll 4
    for (int i = 0; i < 32; i++) {
        const int f  = t + 256 * i;          // 0..8191
        const int kk = f & 127;
        const int j  = f >> 7;               // 0..63
        Ws[kk * 68 + j] = Whh[(size_t)(jt * 64 + j) * H_ + ks * 128 + kk];
    }

    unsigned target = 0;

    for (int s = 0; s < S_; s++) {
        // ---- phase 1a: stage h_prev slice (k-major) ----
        if (s == 0) {
#pragma unroll 4
            for (int i = 0; i < 32; i++) {
                const int f = t + 256 * i;
                Hs[(f & 127) * 68 + (f >> 7)] = 0.f;
            }
        } else {
            const float* hp = out + (size_t)(s - 1) * BH_;
#pragma unroll 4
            for (int i = 0; i < 32; i++) {
                const int f  = t + 256 * i;
                const int kk = f & 127;
                const int b  = f >> 7;
                Hs[kk * 68 + b] = hp[b * H_ + ks * 128 + kk];
            }
        }
        __syncthreads();

        // ---- phase 1b: 64x64x128 partial GEMM, 4x4 microtile ----
        float acc[4][4];
#pragma unroll
        for (int i = 0; i < 4; i++)
#pragma unroll
            for (int j = 0; j < 4; j++) acc[i][j] = 0.f;

#pragma unroll 8
        for (int kk = 0; kk < 128; kk++) {
            const float4 hv = *(const float4*)&Hs[kk * 68 + b0];
            const float4 wv = *(const float4*)&Ws[kk * 68 + j0l];
            const float hb[4] = {hv.x, hv.y, hv.z, hv.w};
            const float wb[4] = {wv.x, wv.y, wv.z, wv.w};
#pragma unroll
            for (int ii = 0; ii < 4; ii++)
#pragma unroll
                for (int jj = 0; jj < 4; jj++)
                    acc[ii][jj] = fmaf(hb[ii], wb[jj], acc[ii][jj]);
        }

        // ---- write partials: g_part[ks][b][j_global] ----
#pragma unroll
        for (int ii = 0; ii < 4; ii++) {
            float4 v;
            v.x = acc[ii][0]; v.y = acc[ii][1]; v.z = acc[ii][2]; v.w = acc[ii][3];
            *(float4*)&g_part[(size_t)(ks * 64 + b0 + ii) * H_ + jt * 64 + j0l] = v;
        }

        grid_bar(target);   // all partials visible

        // ---- phase 2: reduce + bias + xi + tanh, write output slice ----
        {
            const int base = cta * 512;
#pragma unroll
            for (int i = 0; i < 2; i++) {
                const int idx = base + t + 256 * i;      // 0..65535
                const int hh  = idx & (H_ - 1);
                float v = g_xi[(size_t)s * BH_ + idx] + bhh[hh];
#pragma unroll
                for (int q = 0; q < KSPL; q++) v += g_part[q * BH_ + idx];
                const float hval = tanhf(v);
                out[(size_t)s * BH_ + idx] = hval;
                if (s == S_ - 1)
                    out[(size_t)S_ * BH_ + idx] = hval;   // h_final tail
            }
        }

        grid_bar(target);   // h_t visible before next step's staging
    }
}

// =========================================================================
extern "C" void kernel_launch(void* const* d_in, const int* in_sizes, int n_in,
                              void* d_out, int out_size)
{
    (void)in_sizes; (void)n_in; (void)out_size;
    const float* x   = (const float*)d_in[0];
    const float* Wih = (const float*)d_in[1];
    const float* bih = (const float*)d_in[2];
    const float* Whh = (const float*)d_in[3];
    const float* bhh = (const float*)d_in[4];
    float* out = (float*)d_out;

    const int rnn_smem = 2 * 128 * 68 * (int)sizeof(float);   // 69632 B
    cudaFuncSetAttribute(rnn_kernel, cudaFuncAttributeMaxDynamicSharedMemorySize, rnn_smem);
    cudaFuncSetAttribute(gemm_xi_mma, cudaFuncAttributeMaxDynamicSharedMemorySize, GEMM_SMEM);

    init_bar_kernel<<<1, 1>>>();
    gemm_xi_mma<<<dim3(8, 256, 1), 256, GEMM_SMEM>>>(x, Wih, bih);
    rnn_kernel<<<NCTA, 256, rnn_smem>>>(Whh, bhh, out);
}

// round 14
// speedup vs baseline: 1.8380x; 1.5889x over previous
#include <cuda_runtime.h>
#include <cuda_bf16.h>
#include <math.h>
#include <stdint.h>

#define B_   64
#define S_   512
#define H_   1024
#define BH_  (B_ * H_)          // 65536
#define R_   (S_ * B_)          // 32768 time-major rows
#define NCTA 128                // persistent-kernel grid (must be <= #SMs)
#define KSPL 8                  // k-split slices (128 k each)

// ---------------- device scratch (no allocations allowed) ----------------
__device__ float          g_xi[(size_t)R_ * H_];     // 128 MB, time-major (s,b,h)
__device__ __nv_bfloat16  g_xhi[(size_t)R_ * H_];    // 64 MB split x (time-major)
__device__ __nv_bfloat16  g_xlo[(size_t)R_ * H_];    // 64 MB
__device__ __nv_bfloat16  g_whi[(size_t)H_ * H_];    // 2 MB split W_ih
__device__ __nv_bfloat16  g_wlo[(size_t)H_ * H_];    // 2 MB
__device__ __nv_bfloat16  g_hhi[BH_];                // 128 KB split h_t
__device__ __nv_bfloat16  g_hlo[BH_];                // 128 KB
__device__ float          g_part[KSPL * BH_];        // 2 MB partial pre-activations
__device__ unsigned       g_bar;                     // grid barrier counter

__global__ void init_bar_kernel() { g_bar = 0u; }

// zero h split buffers (h_0 = 0); 64 blocks x 256 threads x 1 uint4
__global__ void zero_h_kernel() {
    const int f = blockIdx.x * 256 + threadIdx.x;    // 0..16383 uint4 slots
    if (f < 8192) ((uint4*)g_hhi)[f] = make_uint4(0, 0, 0, 0);
    else          ((uint4*)g_hlo)[f - 8192] = make_uint4(0, 0, 0, 0);
}

// ======================= helpers =======================
__device__ __forceinline__ uint32_t smem_u32(const void* p) {
    uint32_t a;
    asm("{ .reg .u64 t; cvta.to.shared.u64 t, %1; cvt.u32.u64 %0, t; }" : "=r"(a) : "l"(p));
    return a;
}

// fp32x4 -> (bf16 hi x4, bf16 lo x4), each packed as uint2 (mem order)
__device__ __forceinline__ void cvt_split4(float4 v, uint2& hi, uint2& lo) {
    uint32_t h0, h1, l0, l1;
    asm("cvt.rn.satfinite.bf16x2.f32 %0, %1, %2;" : "=r"(h0) : "f"(v.y), "f"(v.x));
    asm("cvt.rn.satfinite.bf16x2.f32 %0, %1, %2;" : "=r"(h1) : "f"(v.w), "f"(v.z));
    float r0 = v.x - __uint_as_float(h0 << 16);
    float r1 = v.y - __uint_as_float(h0 & 0xFFFF0000u);
    float r2 = v.z - __uint_as_float(h1 << 16);
    float r3 = v.w - __uint_as_float(h1 & 0xFFFF0000u);
    asm("cvt.rn.satfinite.bf16x2.f32 %0, %1, %2;" : "=r"(l0) : "f"(r1), "f"(r0));
    asm("cvt.rn.satfinite.bf16x2.f32 %0, %1, %2;" : "=r"(l1) : "f"(r3), "f"(r2));
    hi = make_uint2(h0, h1);
    lo = make_uint2(l0, l1);
}

#define LDMX4(r0, r1, r2, r3, addr) \
    asm volatile("ldmatrix.sync.aligned.m8n8.x4.shared.b16 {%0,%1,%2,%3}, [%4];" \
        : "=r"(r0), "=r"(r1), "=r"(r2), "=r"(r3) : "r"(addr))

#define MMA_BF16(c, a0, a1, a2, a3, b0, b1) \
    asm volatile("mma.sync.aligned.m16n8k16.row.col.f32.bf16.bf16.f32 " \
        "{%0,%1,%2,%3}, {%4,%5,%6,%7}, {%8,%9}, {%0,%1,%2,%3};" \
        : "+f"((c)[0]), "+f"((c)[1]), "+f"((c)[2]), "+f"((c)[3]) \
        : "r"(a0), "r"(a1), "r"(a2), "r"(a3), "r"(b0), "r"(b1))

// =========================================================================
// Pre-pass kernels: one-time fp32 -> bf16 hi/lo split.
// split_x also transposes (b,s) -> time-major row r = s*64+b.
// =========================================================================
__global__ __launch_bounds__(256) void split_x_kernel(const float* __restrict__ x) {
    const int row_in = blockIdx.x;                   // b*512 + s
    const int b = row_in >> 9, s = row_in & 511;
    const size_t r_out = (size_t)(s * 64 + b);
    const int k4 = threadIdx.x * 4;
    const float4 v = *(const float4*)(x + (size_t)row_in * H_ + k4);
    uint2 h, l;
    cvt_split4(v, h, l);
    *(uint2*)(g_xhi + r_out * H_ + k4) = h;
    *(uint2*)(g_xlo + r_out * H_ + k4) = l;
}

__global__ __launch_bounds__(256) void split_w_kernel(const float* __restrict__ Wih) {
    const size_t row = blockIdx.x;
    const int k4 = threadIdx.x * 4;
    const float4 v = *(const float4*)(Wih + row * H_ + k4);
    uint2 h, l;
    cvt_split4(v, h, l);
    *(uint2*)(g_whi + row * H_ + k4) = h;
    *(uint2*)(g_wlo + row * H_ + k4) = l;
}

// =========================================================================
// Kernel 1 (HMMA): xi[r][j] = dot(x_row(r), W_ih[j]) + b_ih[j]
// Grid (8 jt, 256 rt). CTA tile 128x128, K-chunk 64, pure-copy staging from
// pre-split bf16. C = Ahi*Whi + Ahi*Wlo + Alo*Whi, fp32 accumulation.
// =========================================================================
#define KC        64
#define LDSTR     72                         // bf16 elems per SMEM row (pad 8)
#define TILE_ELM  (128 * LDSTR)              // 9216 bf16 per tile
#define GEMM_SMEM (4 * TILE_ELM * 2)         // 73728 bytes

__global__ __launch_bounds__(256, 2) void gemm_xi_mma(const float* __restrict__ bih)
{
    extern __shared__ __nv_bfloat16 smb[];
    __nv_bfloat16* tiles[4] = {smb, smb + TILE_ELM, smb + 2 * TILE_ELM, smb + 3 * TILE_ELM};
    const uint32_t ahi = smem_u32(tiles[0]);
    const uint32_t alo = smem_u32(tiles[1]);
    const uint32_t bhi = smem_u32(tiles[2]);
    const uint32_t blo = smem_u32(tiles[3]);

    const int t      = threadIdx.x;
    const int lane   = t & 31;
    const int wid    = t >> 5;
    const int warp_m = wid >> 2;             // 0..1
    const int warp_n = wid & 3;              // 0..3
    const int jt = blockIdx.x;               // 0..7
    const int rt = blockIdx.y;               // 0..255
    const int r0 = rt * 128;
    const int j0 = jt * 128;

    float acc[4][4][4];
#pragma unroll
    for (int mi = 0; mi < 4; mi++)
#pragma unroll
        for (int ni = 0; ni < 4; ni++)
#pragma unroll
            for (int q = 0; q < 4; q++) acc[mi][ni][q] = 0.f;

    const int a_row = lane & 15;
    const int a_kof = ((lane >> 4) & 1) * 8;
    const int b_row = (lane & 7) + ((lane >> 4) & 1) * 8;
    const int b_kof = ((lane >> 3) & 1) * 8;

    for (int kb = 0; kb < 16; kb++) {
        const int k0 = kb * KC;
        // ---- stage: pure uint4 copy of 4 pre-split tiles ----
#pragma unroll
        for (int i = 0; i < 16; i++) {
            const int f    = t + 256 * i;    // 0..4095 uint4 slots
            const int tile = f >> 10;        // 0..3
            const int g    = f & 1023;
            const int row  = g >> 3;         // 0..127
            const int k8   = (g & 7) * 8;    // 0..56
            const __nv_bfloat16* src =
                (tile == 0) ? g_xhi : (tile == 1) ? g_xlo : (tile == 2) ? g_whi : g_wlo;
            const size_t grow = (size_t)((tile < 2 ? r0 : j0) + row);
            const uint4 v = *(const uint4*)(src + grow * H_ + k0 + k8);
            *(uint4*)(tiles[tile] + row * LDSTR + k8) = v;
        }
        __syncthreads();

        // ---- compute: 4 k16 steps ----
#pragma unroll
        for (int kk = 0; kk < KC; kk += 16) {
            uint32_t bh[8], bl[8];
#pragma unroll
            for (int p = 0; p < 2; p++) {
                const int n0 = warp_n * 32 + p * 16;
                const uint32_t off = (uint32_t)(((n0 + b_row) * LDSTR + kk + b_kof) * 2);
                LDMX4(bh[p*4+0], bh[p*4+1], bh[p*4+2], bh[p*4+3], bhi + off);
                LDMX4(bl[p*4+0], bl[p*4+1], bl[p*4+2], bl[p*4+3], blo + off);
            }
#pragma unroll
            for (int mi = 0; mi < 4; mi++) {
                const int m0 = warp_m * 64 + mi * 16;
                const uint32_t off = (uint32_t)(((m0 + a_row) * LDSTR + kk + a_kof) * 2);
                uint32_t ah0, ah1, ah2, ah3, al0, al1, al2, al3;
                LDMX4(ah0, ah1, ah2, ah3, ahi + off);
                LDMX4(al0, al1, al2, al3, alo + off);
#pragma unroll
                for (int ni = 0; ni < 4; ni++) {
                    MMA_BF16(acc[mi][ni], ah0, ah1, ah2, ah3, bh[ni*2+0], bh[ni*2+1]);
                    MMA_BF16(acc[mi][ni], ah0, ah1, ah2, ah3, bl[ni*2+0], bl[ni*2+1]);
                    MMA_BF16(acc[mi][ni], al0, al1, al2, al3, bh[ni*2+0], bh[ni*2+1]);
                }
            }
        }
        __syncthreads();
    }

    // ---- epilogue: + bias, write g_xi (time-major rows) ----
    const int gr = lane >> 2;
    const int gc = (lane & 3) * 2;
#pragma unroll
    for (int ni = 0; ni < 4; ni++) {
        const int col = j0 + warp_n * 32 + ni * 8 + gc;
        const float bia0 = __ldg(bih + col);
        const float bia1 = __ldg(bih + col + 1);
#pragma unroll
        for (int mi = 0; mi < 4; mi++) {
            const int row = r0 + warp_m * 64 + mi * 16 + gr;
            float2 v0, v1;
            v0.x = acc[mi][ni][0] + bia0;
            v0.y = acc[mi][ni][1] + bia1;
            v1.x = acc[mi][ni][2] + bia0;
            v1.y = acc[mi][ni][3] + bia1;
            *(float2*)(g_xi + (size_t)row * H_ + col)       = v0;
            *(float2*)(g_xi + (size_t)(row + 8) * H_ + col) = v1;
        }
    }
}

// =========================================================================
// Persistent recurrence kernel, HMMA edition.
// 128 CTAs, CTA = (jt: j-tile 64, ks: k-slice 128). W_hh slice split to
// bf16 hi/lo once, SMEM-resident. h_t produced as fp32 (out) + bf16 hi/lo
// (g_hhi/g_hlo). Per step: P[b][j] = h·W^T via 3-term split MMA.
// =========================================================================
#define LD2       136                        // bf16 elems per SMEM row (128 + pad 8)
#define WTILE_ELM (64 * LD2)                 // 8704 elems
#define RNN_SMEM  (4 * WTILE_ELM * 2)        // 69632 bytes

__device__ __forceinline__ void grid_bar(unsigned& target)
{
    target += NCTA;
    __syncthreads();
    if (threadIdx.x == 0) {
        __threadfence();                       // release prior writes
        atomicAdd(&g_bar, 1u);
        while (*(volatile unsigned*)&g_bar < target) { }
        __threadfence();                       // acquire others' writes
    }
    __syncthreads();
}

__global__ __launch_bounds__(256, 1) void rnn_kernel(
    const float* __restrict__ Whh,
    const float* __restrict__ bhh,
    float* __restrict__ out)                   // d_out: (S,B,H) then h_final
{
    extern __shared__ __nv_bfloat16 smr[];
    __nv_bfloat16* Whi = smr;
    __nv_bfloat16* Wlo = smr + WTILE_ELM;
    __nv_bfloat16* Hhi = smr + 2 * WTILE_ELM;
    __nv_bfloat16* Hlo = smr + 3 * WTILE_ELM;
    const uint32_t whi_a = smem_u32(Whi);
    const uint32_t wlo_a = smem_u32(Wlo);
    const uint32_t hhi_a = smem_u32(Hhi);
    const uint32_t hlo_a = smem_u32(Hlo);

    const int t    = threadIdx.x;
    const int lane = t & 31;
    const int wid  = t >> 5;
    const int cta  = blockIdx.x;
    const int jt   = cta >> 3;       // 0..15  (j-tile of 64)
    const int ks   = cta & 7;        // 0..7   (k-slice of 128)
    const int warp_m = wid >> 2;     // 0..1 -> b0w
    const int warp_n = wid & 3;      // 0..3 -> j0w
    const int b0w  = warp_m * 32;
    const int j0w  = warp_n * 16;

    // ldmatrix lane address components
    const int a_row = lane & 15;
    const int a_kof = ((lane >> 4) & 1) * 8;
    const int b_row = (lane & 7) + ((lane >> 4) & 1) * 8;
    const int b_kof = ((lane >> 3) & 1) * 8;

    // ---- one-time: split W_hh slice (64 j x 128 k) into SMEM hi/lo ----
#pragma unroll
    for (int i = 0; i < 8; i++) {
        const int f   = t + 256 * i;         // 0..2047 float4 slots
        const int row = f >> 5;              // 0..63 (j-local)
        const int k4  = (f & 31) * 4;        // 0..124
        const float4 v = *(const float4*)(
            Whh + (size_t)(jt * 64 + row) * H_ + ks * 128 + k4);
        uint2 h, l;
        cvt_split4(v, h, l);
        *(uint2*)(Whi + row * LD2 + k4) = h;
        *(uint2*)(Wlo + row * LD2 + k4) = l;
    }

    unsigned target = 0;

    for (int s = 0; s < S_; s++) {
        // ---- phase 1a: stage h_prev slice (64 b x 128 k, bf16 hi/lo) ----
#pragma unroll
        for (int i = 0; i < 8; i++) {
            const int f   = t + 256 * i;     // 0..2047 uint4 slots
            const int buf = f >> 10;         // 0: hi, 1: lo
            const int g   = f & 1023;
            const int row = g >> 4;          // 0..63 (b)
            const int k8  = (g & 15) * 8;    // 0..120
            const __nv_bfloat16* src = buf ? g_hlo : g_hhi;
            const uint4 v = *(const uint4*)(src + row * H_ + ks * 128 + k8);
            *(uint4*)((buf ? Hlo : Hhi) + row * LD2 + k8) = v;
        }
        __syncthreads();

        // ---- phase 1b: 64x64x128 partial GEMM via 3-term split HMMA ----
        float acc[2][2][4];
#pragma unroll
        for (int mi = 0; mi < 2; mi++)
#pragma unroll
            for (int ni = 0; ni < 2; ni++)
#pragma unroll
                for (int q = 0; q < 4; q++) acc[mi][ni][q] = 0.f;

#pragma unroll
        for (int kk = 0; kk < 128; kk += 16) {
            uint32_t bh[4], bl[4];
            {
                const uint32_t off = (uint32_t)(((j0w + b_row) * LD2 + kk + b_kof) * 2);
                LDMX4(bh[0], bh[1], bh[2], bh[3], whi_a + off);
                LDMX4(bl[0], bl[1], bl[2], bl[3], wlo_a + off);
            }
#pragma unroll
            for (int mi = 0; mi < 2; mi++) {
                const uint32_t off = (uint32_t)(((b0w + mi * 16 + a_row) * LD2 + kk + a_kof) * 2);
                uint32_t ah0, ah1, ah2, ah3, al0, al1, al2, al3;
                LDMX4(ah0, ah1, ah2, ah3, hhi_a + off);
                LDMX4(al0, al1, al2, al3, hlo_a + off);
#pragma unroll
                for (int ni = 0; ni < 2; ni++) {
                    MMA_BF16(acc[mi][ni], ah0, ah1, ah2, ah3, bh[ni*2+0], bh[ni*2+1]);
                    MMA_BF16(acc[mi][ni], ah0, ah1, ah2, ah3, bl[ni*2+0], bl[ni*2+1]);
                    MMA_BF16(acc[mi][ni], al0, al1, al2, al3, bh[ni*2+0], bh[ni*2+1]);
                }
            }
        }

        // ---- write partials: g_part[ks*64 + b][j_global] ----
        {
            const int gr = lane >> 2;
            const int gc = (lane & 3) * 2;
#pragma unroll
            for (int mi = 0; mi < 2; mi++)
#pragma unroll
                for (int ni = 0; ni < 2; ni++) {
                    const int row = b0w + mi * 16 + gr;
                    const int col = jt * 64 + j0w + ni * 8 + gc;
                    float2 v0, v1;
                    v0.x = acc[mi][ni][0]; v0.y = acc[mi][ni][1];
                    v1.x = acc[mi][ni][2]; v1.y = acc[mi][ni][3];
                    *(float2*)&g_part[(size_t)(ks * 64 + row) * H_ + col]     = v0;
                    *(float2*)&g_part[(size_t)(ks * 64 + row + 8) * H_ + col] = v1;
                }
        }

        grid_bar(target);   // all partials visible

        // ---- phase 2: reduce + bias + xi + tanh; write out + split h ----
        {
            const int base = cta * 512;
#pragma unroll
            for (int i = 0; i < 2; i++) {
                const int idx = base + t + 256 * i;      // 0..65535 (b*H + h)
                const int hh  = idx & (H_ - 1);
                float v = g_xi[(size_t)s * BH_ + idx] + bhh[hh];
#pragma unroll
                for (int q = 0; q < KSPL; q++) v += g_part[q * BH_ + idx];
                const float hval = tanhf(v);
                out[(size_t)s * BH_ + idx] = hval;
                const __nv_bfloat16 hb = __float2bfloat16_rn(hval);
                g_hhi[idx] = hb;
                g_hlo[idx] = __float2bfloat16_rn(hval - __bfloat162float(hb));
                if (s == S_ - 1)
                    out[(size_t)S_ * BH_ + idx] = hval;   // h_final tail
            }
        }

        grid_bar(target);   // h_t visible before next step's staging
    }
}

// =========================================================================
extern "C" void kernel_launch(void* const* d_in, const int* in_sizes, int n_in,
                              void* d_out, int out_size)
{
    (void)in_sizes; (void)n_in; (void)out_size;
    const float* x   = (const float*)d_in[0];
    const float* Wih = (const float*)d_in[1];
    const float* bih = (const float*)d_in[2];
    const float* Whh = (const float*)d_in[3];
    const float* bhh = (const float*)d_in[4];
    float* out = (float*)d_out;

    cudaFuncSetAttribute(rnn_kernel,  cudaFuncAttributeMaxDynamicSharedMemorySize, RNN_SMEM);
    cudaFuncSetAttribute(gemm_xi_mma, cudaFuncAttributeMaxDynamicSharedMemorySize, GEMM_SMEM);

    init_bar_kernel<<<1, 1>>>();
    zero_h_kernel<<<64, 256>>>();
    split_x_kernel<<<R_, 256>>>(x);
    split_w_kernel<<<H_, 256>>>(Wih);
    gemm_xi_mma<<<dim3(8, 256, 1), 256, GEMM_SMEM>>>(bih);
    rnn_kernel<<<NCTA, 256, RNN_SMEM>>>(Whh, bhh, out);
}

// round 15
// speedup vs baseline: 1.9450x; 1.0582x over previous
#include <cuda_runtime.h>
#include <cuda_bf16.h>
#include <math.h>
#include <stdint.h>

#define B_   64
#define S_   512
#define H_   1024
#define BH_  (B_ * H_)          // 65536
#define R_   (S_ * B_)          // 32768 time-major rows
#define NCTA 128                // persistent-kernel grid (must be <= #SMs)
#define KSPL 8                  // k-split slices (128 k each)

// ---------------- device scratch (no allocations allowed) ----------------
__device__ float          g_xi[(size_t)R_ * H_];     // 128 MB, time-major (s,b,h)
__device__ __nv_bfloat16  g_xhi[(size_t)R_ * H_];    // 64 MB split x (time-major)
__device__ __nv_bfloat16  g_xlo[(size_t)R_ * H_];    // 64 MB
__device__ __nv_bfloat16  g_whi[(size_t)H_ * H_];    // 2 MB split W_ih
__device__ __nv_bfloat16  g_wlo[(size_t)H_ * H_];    // 2 MB
__device__ __nv_bfloat16  g_hh[2][2][BH_];           // h split, [parity][hi/lo]
__device__ float          g_p[2][KSPL * BH_];        // partials, double-buffered
__device__ unsigned       g_pflag[16];               // partials-ready, per j-group
__device__ unsigned       g_hflag[8];                // h-ready, per k-slice

__global__ void init_flags_kernel() {
    if (threadIdx.x < 16) g_pflag[threadIdx.x] = 0u;
    if (threadIdx.x < 8)  g_hflag[threadIdx.x] = 0u;
}

// ======================= helpers =======================
__device__ __forceinline__ uint32_t smem_u32(const void* p) {
    uint32_t a;
    asm("{ .reg .u64 t; cvta.to.shared.u64 t, %1; cvt.u32.u64 %0, t; }" : "=r"(a) : "l"(p));
    return a;
}

// fp32x4 -> (bf16 hi x4, bf16 lo x4), each packed as uint2 (mem order)
__device__ __forceinline__ void cvt_split4(float4 v, uint2& hi, uint2& lo) {
    uint32_t h0, h1, l0, l1;
    asm("cvt.rn.satfinite.bf16x2.f32 %0, %1, %2;" : "=r"(h0) : "f"(v.y), "f"(v.x));
    asm("cvt.rn.satfinite.bf16x2.f32 %0, %1, %2;" : "=r"(h1) : "f"(v.w), "f"(v.z));
    float r0 = v.x - __uint_as_float(h0 << 16);
    float r1 = v.y - __uint_as_float(h0 & 0xFFFF0000u);
    float r2 = v.z - __uint_as_float(h1 << 16);
    float r3 = v.w - __uint_as_float(h1 & 0xFFFF0000u);
    asm("cvt.rn.satfinite.bf16x2.f32 %0, %1, %2;" : "=r"(l0) : "f"(r1), "f"(r0));
    asm("cvt.rn.satfinite.bf16x2.f32 %0, %1, %2;" : "=r"(l1) : "f"(r3), "f"(r2));
    hi = make_uint2(h0, h1);
    lo = make_uint2(l0, l1);
}

#define LDMX4(r0, r1, r2, r3, addr) \
    asm volatile("ldmatrix.sync.aligned.m8n8.x4.shared.b16 {%0,%1,%2,%3}, [%4];" \
        : "=r"(r0), "=r"(r1), "=r"(r2), "=r"(r3) : "r"(addr))

#define MMA_BF16(c, a0, a1, a2, a3, b0, b1) \
    asm volatile("mma.sync.aligned.m16n8k16.row.col.f32.bf16.bf16.f32 " \
        "{%0,%1,%2,%3}, {%4,%5,%6,%7}, {%8,%9}, {%0,%1,%2,%3};" \
        : "+f"((c)[0]), "+f"((c)[1]), "+f"((c)[2]), "+f"((c)[3]) \
        : "r"(a0), "r"(a1), "r"(a2), "r"(a3), "r"(b0), "r"(b1))

// =========================================================================
// Pre-pass kernels: one-time fp32 -> bf16 hi/lo split.
// split_x also transposes (b,s) -> time-major row r = s*64+b.
// =========================================================================
__global__ __launch_bounds__(256) void split_x_kernel(const float* __restrict__ x) {
    const int row_in = blockIdx.x;                   // b*512 + s
    const int b = row_in >> 9, s = row_in & 511;
    const size_t r_out = (size_t)(s * 64 + b);
    const int k4 = threadIdx.x * 4;
    const float4 v = *(const float4*)(x + (size_t)row_in * H_ + k4);
    uint2 h, l;
    cvt_split4(v, h, l);
    *(uint2*)(g_xhi + r_out * H_ + k4) = h;
    *(uint2*)(g_xlo + r_out * H_ + k4) = l;
}

__global__ __launch_bounds__(256) void split_w_kernel(const float* __restrict__ Wih) {
    const size_t row = blockIdx.x;
    const int k4 = threadIdx.x * 4;
    const float4 v = *(const float4*)(Wih + row * H_ + k4);
    uint2 h, l;
    cvt_split4(v, h, l);
    *(uint2*)(g_whi + row * H_ + k4) = h;
    *(uint2*)(g_wlo + row * H_ + k4) = l;
}

// =========================================================================
// Kernel 1 (HMMA): xi[r][j] = dot(x_row(r), W_ih[j]) + b_ih[j]
// Grid (8 jt, 256 rt). CTA tile 128x128, K-chunk 64, pure-copy staging from
// pre-split bf16. C = Ahi*Whi + Ahi*Wlo + Alo*Whi, fp32 accumulation.
// =========================================================================
#define KC        64
#define LDSTR     72                         // bf16 elems per SMEM row (pad 8)
#define TILE_ELM  (128 * LDSTR)              // 9216 bf16 per tile
#define GEMM_SMEM (4 * TILE_ELM * 2)         // 73728 bytes

__global__ __launch_bounds__(256, 2) void gemm_xi_mma(const float* __restrict__ bih)
{
    extern __shared__ __nv_bfloat16 smb[];
    __nv_bfloat16* tiles[4] = {smb, smb + TILE_ELM, smb + 2 * TILE_ELM, smb + 3 * TILE_ELM};
    const uint32_t ahi = smem_u32(tiles[0]);
    const uint32_t alo = smem_u32(tiles[1]);
    const uint32_t bhi = smem_u32(tiles[2]);
    const uint32_t blo = smem_u32(tiles[3]);

    const int t      = threadIdx.x;
    const int lane   = t & 31;
    const int wid    = t >> 5;
    const int warp_m = wid >> 2;             // 0..1
    const int warp_n = wid & 3;              // 0..3
    const int jt = blockIdx.x;               // 0..7
    const int rt = blockIdx.y;               // 0..255
    const int r0 = rt * 128;
    const int j0 = jt * 128;

    float acc[4][4][4];
#pragma unroll
    for (int mi = 0; mi < 4; mi++)
#pragma unroll
        for (int ni = 0; ni < 4; ni++)
#pragma unroll
            for (int q = 0; q < 4; q++) acc[mi][ni][q] = 0.f;

    const int a_row = lane & 15;
    const int a_kof = ((lane >> 4) & 1) * 8;
    const int b_row = (lane & 7) + ((lane >> 4) & 1) * 8;
    const int b_kof = ((lane >> 3) & 1) * 8;

    for (int kb = 0; kb < 16; kb++) {
        const int k0 = kb * KC;
        // ---- stage: pure uint4 copy of 4 pre-split tiles ----
#pragma unroll
        for (int i = 0; i < 16; i++) {
            const int f    = t + 256 * i;    // 0..4095 uint4 slots
            const int tile = f >> 10;        // 0..3
            const int g    = f & 1023;
            const int row  = g >> 3;         // 0..127
            const int k8   = (g & 7) * 8;    // 0..56
            const __nv_bfloat16* src =
                (tile == 0) ? g_xhi : (tile == 1) ? g_xlo : (tile == 2) ? g_whi : g_wlo;
            const size_t grow = (size_t)((tile < 2 ? r0 : j0) + row);
            const uint4 v = *(const uint4*)(src + grow * H_ + k0 + k8);
            *(uint4*)(tiles[tile] + row * LDSTR + k8) = v;
        }
        __syncthreads();

        // ---- compute: 4 k16 steps ----
#pragma unroll
        for (int kk = 0; kk < KC; kk += 16) {
            uint32_t bh[8], bl[8];
#pragma unroll
            for (int p = 0; p < 2; p++) {
                const int n0 = warp_n * 32 + p * 16;
                const uint32_t off = (uint32_t)(((n0 + b_row) * LDSTR + kk + b_kof) * 2);
                LDMX4(bh[p*4+0], bh[p*4+1], bh[p*4+2], bh[p*4+3], bhi + off);
                LDMX4(bl[p*4+0], bl[p*4+1], bl[p*4+2], bl[p*4+3], blo + off);
            }
#pragma unroll
            for (int mi = 0; mi < 4; mi++) {
                const int m0 = warp_m * 64 + mi * 16;
                const uint32_t off = (uint32_t)(((m0 + a_row) * LDSTR + kk + a_kof) * 2);
                uint32_t ah0, ah1, ah2, ah3, al0, al1, al2, al3;
                LDMX4(ah0, ah1, ah2, ah3, ahi + off);
                LDMX4(al0, al1, al2, al3, alo + off);
#pragma unroll
                for (int ni = 0; ni < 4; ni++) {
                    MMA_BF16(acc[mi][ni], ah0, ah1, ah2, ah3, bh[ni*2+0], bh[ni*2+1]);
                    MMA_BF16(acc[mi][ni], ah0, ah1, ah2, ah3, bl[ni*2+0], bl[ni*2+1]);
                    MMA_BF16(acc[mi][ni], al0, al1, al2, al3, bh[ni*2+0], bh[ni*2+1]);
                }
            }
        }
        __syncthreads();
    }

    // ---- epilogue: + bias, write g_xi (time-major rows) ----
    const int gr = lane >> 2;
    const int gc = (lane & 3) * 2;
#pragma unroll
    for (int ni = 0; ni < 4; ni++) {
        const int col = j0 + warp_n * 32 + ni * 8 + gc;
        const float bia0 = __ldg(bih + col);
        const float bia1 = __ldg(bih + col + 1);
#pragma unroll
        for (int mi = 0; mi < 4; mi++) {
            const int row = r0 + warp_m * 64 + mi * 16 + gr;
            float2 v0, v1;
            v0.x = acc[mi][ni][0] + bia0;
            v0.y = acc[mi][ni][1] + bia1;
            v1.x = acc[mi][ni][2] + bia0;
            v1.y = acc[mi][ni][3] + bia1;
            *(float2*)(g_xi + (size_t)row * H_ + col)       = v0;
            *(float2*)(g_xi + (size_t)(row + 8) * H_ + col) = v1;
        }
    }
}

// =========================================================================
// Persistent recurrence kernel, flag-pipelined (no full-grid barriers).
// MMA role:    CTA c = (jt = c>>3 : j-tile 64, ks = c&7 : k-slice 128).
// Reduce role: CTA c owns h-columns [8c, 8c+8) for all 64 b.
//   partials for cols of group jt come from the 8 CTAs with c>>3 == jt
//     -> g_pflag[jt] (+8 per step)
//   h cols [8c,8c+8) feed k-slice ks = c>>4 stagers
//     -> g_hflag[c>>4] (+16 per step)
// Double-buffered partials (parity s&1) + double-buffered h split buffers.
// =========================================================================
#define LD2       136                        // bf16 elems per SMEM row (128 + pad 8)
#define WTILE_ELM (64 * LD2)                 // 8704 elems
#define RNN_SMEM  (4 * WTILE_ELM * 2)        // 69632 bytes

__global__ __launch_bounds__(256, 1) void rnn_kernel(
    const float* __restrict__ Whh,
    const float* __restrict__ bhh,
    float* __restrict__ out)                   // d_out: (S,B,H) then h_final
{
    extern __shared__ __nv_bfloat16 smr[];
    __nv_bfloat16* Whi = smr;
    __nv_bfloat16* Wlo = smr + WTILE_ELM;
    __nv_bfloat16* Hhi = smr + 2 * WTILE_ELM;
    __nv_bfloat16* Hlo = smr + 3 * WTILE_ELM;
    const uint32_t whi_a = smem_u32(Whi);
    const uint32_t wlo_a = smem_u32(Wlo);
    const uint32_t hhi_a = smem_u32(Hhi);
    const uint32_t hlo_a = smem_u32(Hlo);

    const int t    = threadIdx.x;
    const int lane = t & 31;
    const int wid  = t >> 5;
    const int cta  = blockIdx.x;
    const int jt   = cta >> 3;       // 0..15  (j-tile of 64)
    const int ks   = cta & 7;        // 0..7   (k-slice of 128)
    const int warp_m = wid >> 2;     // 0..1 -> b0w
    const int warp_n = wid & 3;      // 0..3 -> j0w
    const int b0w  = warp_m * 32;
    const int j0w  = warp_n * 16;

    // ldmatrix lane address components
    const int a_row = lane & 15;
    const int a_kof = ((lane >> 4) & 1) * 8;
    const int b_row = (lane & 7) + ((lane >> 4) & 1) * 8;
    const int b_kof = ((lane >> 3) & 1) * 8;

    // reducer role constants: col block [cta*8, cta*8+8), float2 per thread
    const int rb  = t >> 2;                  // 0..63 (batch)
    const int rc  = (t & 3) << 1;            // 0,2,4,6
    const int col = cta * 8 + rc;
    const size_t oidx = ((size_t)rb << 10) + col;
    const float bh0 = bhh[col];
    const float bh1 = bhh[col + 1];

    // ---- one-time: split W_hh slice (64 j x 128 k) into SMEM hi/lo ----
#pragma unroll
    for (int i = 0; i < 8; i++) {
        const int f   = t + 256 * i;         // 0..2047 float4 slots
        const int row = f >> 5;              // 0..63 (j-local)
        const int k4  = (f & 31) * 4;        // 0..124
        const float4 v = *(const float4*)(
            Whh + (size_t)(jt * 64 + row) * H_ + ks * 128 + k4);
        uint2 h, l;
        cvt_split4(v, h, l);
        *(uint2*)(Whi + row * LD2 + k4) = h;
        *(uint2*)(Wlo + row * LD2 + k4) = l;
    }

    for (int s = 0; s < S_; s++) {
        // ---- A: prefetch xi(s) for reduce role (independent of all gates) ----
        const float2 xi2 = *(const float2*)(g_xi + (size_t)s * BH_ + oidx);

        // ---- B: gate staging on producers of h(s-1) ----
        if (s > 0) {
            if (t == 0) {
                const unsigned tgt = 16u * (unsigned)s;
                while (*(volatile unsigned*)&g_hflag[ks] < tgt) { }
                __threadfence();
            }
            __syncthreads();
        }

        // ---- C: stage h(s-1) slice (64 b x 128 k, bf16 hi/lo) ----
        if (s == 0) {
#pragma unroll
            for (int i = 0; i < 8; i++) {
                const int f = t + 256 * i;
                const int buf = f >> 10;
                const int g = f & 1023;
                *(uint4*)((buf ? Hlo : Hhi) + (g >> 4) * LD2 + (g & 15) * 8) =
                    make_uint4(0, 0, 0, 0);
            }
        } else {
            const __nv_bfloat16* hsrc_hi = g_hh[(s + 1) & 1][0];
            const __nv_bfloat16* hsrc_lo = g_hh[(s + 1) & 1][1];
#pragma unroll
            for (int i = 0; i < 8; i++) {
                const int f   = t + 256 * i;     // 0..2047 uint4 slots
                const int buf = f >> 10;         // 0: hi, 1: lo
                const int g   = f & 1023;
                const int row = g >> 4;          // 0..63 (b)
                const int k8  = (g & 15) * 8;    // 0..120
                const __nv_bfloat16* src = buf ? hsrc_lo : hsrc_hi;
                const uint4 v = *(const uint4*)(src + row * H_ + ks * 128 + k8);
                *(uint4*)((buf ? Hlo : Hhi) + row * LD2 + k8) = v;
            }
        }
        __syncthreads();

        // ---- D: 64x64x128 partial GEMM via 3-term split HMMA ----
        float acc[2][2][4];
#pragma unroll
        for (int mi = 0; mi < 2; mi++)
#pragma unroll
            for (int ni = 0; ni < 2; ni++)
#pragma unroll
                for (int q = 0; q < 4; q++) acc[mi][ni][q] = 0.f;

#pragma unroll
        for (int kk = 0; kk < 128; kk += 16) {
            uint32_t bh[4], bl[4];
            {
                const uint32_t off = (uint32_t)(((j0w + b_row) * LD2 + kk + b_kof) * 2);
                LDMX4(bh[0], bh[1], bh[2], bh[3], whi_a + off);
                LDMX4(bl[0], bl[1], bl[2], bl[3], wlo_a + off);
            }
#pragma unroll
            for (int mi = 0; mi < 2; mi++) {
                const uint32_t off = (uint32_t)(((b0w + mi * 16 + a_row) * LD2 + kk + a_kof) * 2);
                uint32_t ah0, ah1, ah2, ah3, al0, al1, al2, al3;
                LDMX4(ah0, ah1, ah2, ah3, hhi_a + off);
                LDMX4(al0, al1, al2, al3, hlo_a + off);
#pragma unroll
                for (int ni = 0; ni < 2; ni++) {
                    MMA_BF16(acc[mi][ni], ah0, ah1, ah2, ah3, bh[ni*2+0], bh[ni*2+1]);
                    MMA_BF16(acc[mi][ni], ah0, ah1, ah2, ah3, bl[ni*2+0], bl[ni*2+1]);
                    MMA_BF16(acc[mi][ni], al0, al1, al2, al3, bh[ni*2+0], bh[ni*2+1]);
                }
            }
        }

        // ---- E: write partials into parity buffer ----
        {
            float* pb = g_p[s & 1];
            const int gr = lane >> 2;
            const int gc = (lane & 3) * 2;
#pragma unroll
            for (int mi = 0; mi < 2; mi++)
#pragma unroll
                for (int ni = 0; ni < 2; ni++) {
                    const int row = b0w + mi * 16 + gr;
                    const int pcol = jt * 64 + j0w + ni * 8 + gc;
                    float2 v0, v1;
                    v0.x = acc[mi][ni][0]; v0.y = acc[mi][ni][1];
                    v1.x = acc[mi][ni][2]; v1.y = acc[mi][ni][3];
                    *(float2*)&pb[(size_t)(ks * 64 + row) * H_ + pcol]     = v0;
                    *(float2*)&pb[(size_t)(ks * 64 + row + 8) * H_ + pcol] = v1;
                }
        }

        // ---- F: signal partials ready ----
        __syncthreads();
        if (t == 0) {
            __threadfence();
            atomicAdd(&g_pflag[jt], 1u);
        }

        // ---- G: gate reduce on own j-group partials ----
        if (t == 0) {
            const unsigned tgt = 8u * (unsigned)(s + 1);
            while (*(volatile unsigned*)&g_pflag[jt] < tgt) { }
            __threadfence();
        }
        __syncthreads();

        // ---- H: reduce + bias + xi + tanh; write out + split h ----
        {
            float v0 = xi2.x + bh0;
            float v1 = xi2.y + bh1;
            const float* pb = g_p[s & 1];
#pragma unroll
            for (int q = 0; q < KSPL; q++) {
                const float2 p = *(const float2*)(pb + (size_t)q * BH_ + oidx);
                v0 += p.x; v1 += p.y;
            }
            const float h0 = tanhf(v0);
            const float h1 = tanhf(v1);
            float2 ho; ho.x = h0; ho.y = h1;
            *(float2*)(out + (size_t)s * BH_ + oidx) = ho;
            __nv_bfloat162 hb;
            hb.x = __float2bfloat16_rn(h0);
            hb.y = __float2bfloat16_rn(h1);
            *(__nv_bfloat162*)(g_hh[s & 1][0] + oidx) = hb;
            __nv_bfloat162 lb;
            lb.x = __float2bfloat16_rn(h0 - __bfloat162float(hb.x));
            lb.y = __float2bfloat16_rn(h1 - __bfloat162float(hb.y));
            *(__nv_bfloat162*)(g_hh[s & 1][1] + oidx) = lb;
            if (s == S_ - 1)
                *(float2*)(out + (size_t)S_ * BH_ + oidx) = ho;
        }

        // ---- I: signal h ready ----
        __syncthreads();
        if (t == 0) {
            __threadfence();
            atomicAdd(&g_hflag[cta >> 4], 1u);
        }
    }
}

// =========================================================================
extern "C" void kernel_launch(void* const* d_in, const int* in_sizes, int n_in,
                              void* d_out, int out_size)
{
    (void)in_sizes; (void)n_in; (void)out_size;
    const float* x   = (const float*)d_in[0];
    const float* Wih = (const float*)d_in[1];
    const float* bih = (const float*)d_in[2];
    const float* Whh = (const float*)d_in[3];
    const float* bhh = (const float*)d_in[4];
    float* out = (float*)d_out;

    cudaFuncSetAttribute(rnn_kernel,  cudaFuncAttributeMaxDynamicSharedMemorySize, RNN_SMEM);
    cudaFuncSetAttribute(gemm_xi_mma, cudaFuncAttributeMaxDynamicSharedMemorySize, GEMM_SMEM);

    init_flags_kernel<<<1, 32>>>();
    split_x_kernel<<<R_, 256>>>(x);
    split_w_kernel<<<H_, 256>>>(Wih);
    gemm_xi_mma<<<dim3(8, 256, 1), 256, GEMM_SMEM>>>(bih);
    rnn_kernel<<<NCTA, 256, RNN_SMEM>>>(Whh, bhh, out);
}

// round 16
// speedup vs baseline: 2.3376x; 1.2019x over previous
#include <cuda_runtime.h>
#include <cuda_bf16.h>
#include <math.h>
#include <stdint.h>

#define B_   64
#define S_   512
#define H_   1024
#define BH_  (B_ * H_)          // 65536
#define R_   (S_ * B_)          // 32768 time-major rows
#define NCTA 128

// ---------------- device scratch (no allocations allowed) ----------------
__device__ float          g_xi[(size_t)R_ * H_];     // 128 MB, time-major (s,b,h)
__device__ __nv_bfloat16  g_xhi[(size_t)R_ * H_];    // 64 MB split x (time-major)
__device__ __nv_bfloat16  g_xlo[(size_t)R_ * H_];    // 64 MB
__device__ __nv_bfloat16  g_whi[(size_t)H_ * H_];    // 2 MB split W_ih
__device__ __nv_bfloat16  g_wlo[(size_t)H_ * H_];    // 2 MB
__device__ __nv_bfloat16  g_hh[2][2][BH_];           // h split, [parity][hi/lo]
__device__ unsigned       g_hflag[4];                // h-ready, per b-group

__global__ void init_flags_kernel() {
    if (threadIdx.x < 4) g_hflag[threadIdx.x] = 0u;
}

// ======================= helpers =======================
__device__ __forceinline__ uint32_t smem_u32(const void* p) {
    uint32_t a;
    asm("{ .reg .u64 t; cvta.to.shared.u64 t, %1; cvt.u32.u64 %0, t; }" : "=r"(a) : "l"(p));
    return a;
}

// fp32x4 -> (bf16 hi x4, bf16 lo x4), each packed as uint2 (mem order)
__device__ __forceinline__ void cvt_split4(float4 v, uint2& hi, uint2& lo) {
    uint32_t h0, h1, l0, l1;
    asm("cvt.rn.satfinite.bf16x2.f32 %0, %1, %2;" : "=r"(h0) : "f"(v.y), "f"(v.x));
    asm("cvt.rn.satfinite.bf16x2.f32 %0, %1, %2;" : "=r"(h1) : "f"(v.w), "f"(v.z));
    float r0 = v.x - __uint_as_float(h0 << 16);
    float r1 = v.y - __uint_as_float(h0 & 0xFFFF0000u);
    float r2 = v.z - __uint_as_float(h1 << 16);
    float r3 = v.w - __uint_as_float(h1 & 0xFFFF0000u);
    asm("cvt.rn.satfinite.bf16x2.f32 %0, %1, %2;" : "=r"(l0) : "f"(r1), "f"(r0));
    asm("cvt.rn.satfinite.bf16x2.f32 %0, %1, %2;" : "=r"(l1) : "f"(r3), "f"(r2));
    hi = make_uint2(h0, h1);
    lo = make_uint2(l0, l1);
}

#define LDMX4(r0, r1, r2, r3, addr) \
    asm volatile("ldmatrix.sync.aligned.m8n8.x4.shared.b16 {%0,%1,%2,%3}, [%4];" \
        : "=r"(r0), "=r"(r1), "=r"(r2), "=r"(r3) : "r"(addr))

#define MMA_BF16(c, a0, a1, a2, a3, b0, b1) \
    asm volatile("mma.sync.aligned.m16n8k16.row.col.f32.bf16.bf16.f32 " \
        "{%0,%1,%2,%3}, {%4,%5,%6,%7}, {%8,%9}, {%0,%1,%2,%3};" \
        : "+f"((c)[0]), "+f"((c)[1]), "+f"((c)[2]), "+f"((c)[3]) \
        : "r"(a0), "r"(a1), "r"(a2), "r"(a3), "r"(b0), "r"(b1))

// =========================================================================
// Pre-pass kernels: one-time fp32 -> bf16 hi/lo split.
// =========================================================================
__global__ __launch_bounds__(256) void split_x_kernel(const float* __restrict__ x) {
    const int row_in = blockIdx.x;                   // b*512 + s
    const int b = row_in >> 9, s = row_in & 511;
    const size_t r_out = (size_t)(s * 64 + b);
    const int k4 = threadIdx.x * 4;
    const float4 v = *(const float4*)(x + (size_t)row_in * H_ + k4);
    uint2 h, l;
    cvt_split4(v, h, l);
    *(uint2*)(g_xhi + r_out * H_ + k4) = h;
    *(uint2*)(g_xlo + r_out * H_ + k4) = l;
}

__global__ __launch_bounds__(256) void split_w_kernel(const float* __restrict__ Wih) {
    const size_t row = blockIdx.x;
    const int k4 = threadIdx.x * 4;
    const float4 v = *(const float4*)(Wih + row * H_ + k4);
    uint2 h, l;
    cvt_split4(v, h, l);
    *(uint2*)(g_whi + row * H_ + k4) = h;
    *(uint2*)(g_wlo + row * H_ + k4) = l;
}

// =========================================================================
// Kernel 1 (HMMA): xi GEMM — unchanged from R14/R15 (510us, tensor 66.6%).
// =========================================================================
#define KC        64
#define LDSTR     72
#define TILE_ELM  (128 * LDSTR)
#define GEMM_SMEM (4 * TILE_ELM * 2)

__global__ __launch_bounds__(256, 2) void gemm_xi_mma(const float* __restrict__ bih)
{
    extern __shared__ __nv_bfloat16 smb[];
    __nv_bfloat16* tiles[4] = {smb, smb + TILE_ELM, smb + 2 * TILE_ELM, smb + 3 * TILE_ELM};
    const uint32_t ahi = smem_u32(tiles[0]);
    const uint32_t alo = smem_u32(tiles[1]);
    const uint32_t bhi = smem_u32(tiles[2]);
    const uint32_t blo = smem_u32(tiles[3]);

    const int t      = threadIdx.x;
    const int lane   = t & 31;
    const int wid    = t >> 5;
    const int warp_m = wid >> 2;
    const int warp_n = wid & 3;
    const int jt = blockIdx.x;
    const int rt = blockIdx.y;
    const int r0 = rt * 128;
    const int j0 = jt * 128;

    float acc[4][4][4];
#pragma unroll
    for (int mi = 0; mi < 4; mi++)
#pragma unroll
        for (int ni = 0; ni < 4; ni++)
#pragma unroll
            for (int q = 0; q < 4; q++) acc[mi][ni][q] = 0.f;

    const int a_row = lane & 15;
    const int a_kof = ((lane >> 4) & 1) * 8;
    const int b_row = (lane & 7) + ((lane >> 4) & 1) * 8;
    const int b_kof = ((lane >> 3) & 1) * 8;

    for (int kb = 0; kb < 16; kb++) {
        const int k0 = kb * KC;
#pragma unroll
        for (int i = 0; i < 16; i++) {
            const int f    = t + 256 * i;
            const int tile = f >> 10;
            const int g    = f & 1023;
            const int row  = g >> 3;
            const int k8   = (g & 7) * 8;
            const __nv_bfloat16* src =
                (tile == 0) ? g_xhi : (tile == 1) ? g_xlo : (tile == 2) ? g_whi : g_wlo;
            const size_t grow = (size_t)((tile < 2 ? r0 : j0) + row);
            const uint4 v = *(const uint4*)(src + grow * H_ + k0 + k8);
            *(uint4*)(tiles[tile] + row * LDSTR + k8) = v;
        }
        __syncthreads();

#pragma unroll
        for (int kk = 0; kk < KC; kk += 16) {
            uint32_t bh[8], bl[8];
#pragma unroll
            for (int p = 0; p < 2; p++) {
                const int n0 = warp_n * 32 + p * 16;
                const uint32_t off = (uint32_t)(((n0 + b_row) * LDSTR + kk + b_kof) * 2);
                LDMX4(bh[p*4+0], bh[p*4+1], bh[p*4+2], bh[p*4+3], bhi + off);
                LDMX4(bl[p*4+0], bl[p*4+1], bl[p*4+2], bl[p*4+3], blo + off);
            }
#pragma unroll
            for (int mi = 0; mi < 4; mi++) {
                const int m0 = warp_m * 64 + mi * 16;
                const uint32_t off = (uint32_t)(((m0 + a_row) * LDSTR + kk + a_kof) * 2);
                uint32_t ah0, ah1, ah2, ah3, al0, al1, al2, al3;
                LDMX4(ah0, ah1, ah2, ah3, ahi + off);
                LDMX4(al0, al1, al2, al3, alo + off);
#pragma unroll
                for (int ni = 0; ni < 4; ni++) {
                    MMA_BF16(acc[mi][ni], ah0, ah1, ah2, ah3, bh[ni*2+0], bh[ni*2+1]);
                    MMA_BF16(acc[mi][ni], ah0, ah1, ah2, ah3, bl[ni*2+0], bl[ni*2+1]);
                    MMA_BF16(acc[mi][ni], al0, al1, al2, al3, bh[ni*2+0], bh[ni*2+1]);
                }
            }
        }
        __syncthreads();
    }

    const int gr = lane >> 2;
    const int gc = (lane & 3) * 2;
#pragma unroll
    for (int ni = 0; ni < 4; ni++) {
        const int col = j0 + warp_n * 32 + ni * 8 + gc;
        const float bia0 = __ldg(bih + col);
        const float bia1 = __ldg(bih + col + 1);
#pragma unroll
        for (int mi = 0; mi < 4; mi++) {
            const int row = r0 + warp_m * 64 + mi * 16 + gr;
            float2 v0, v1;
            v0.x = acc[mi][ni][0] + bia0;
            v0.y = acc[mi][ni][1] + bia1;
            v1.x = acc[mi][ni][2] + bia0;
            v1.y = acc[mi][ni][3] + bia1;
            *(float2*)(g_xi + (size_t)row * H_ + col)       = v0;
            *(float2*)(g_xi + (size_t)(row + 8) * H_ + col) = v1;
        }
    }
}

// =========================================================================
// Persistent recurrence, full-K per CTA (no partials hop).
// 128 CTAs = 32 jt (32 j cols) x 4 bt (16 b rows). W_hh tile (32j x 1024k,
// bf16 hi/lo) SMEM-resident. Per step: each warp w stages h(s-1)[16b x
// k in [128w,128w+128)] privately (warp-level gate, no block sync), runs
// m16 n32 k128 x 3-term split HMMA, deposits 16x32 fp32 partial in SMEM;
// block-reduce over 8 warps + xi + bias -> tanh -> h block (16b x 32j) to
// GMEM; one flag per bt group (fan-in 32).
// =========================================================================
#define WJ_   32                              // j cols per CTA
#define WB_   16                              // b rows per CTA
#define WSTR  1032                            // W row stride (1024 + 8)
#define HSTR  136                             // h row stride per warp (128 + 8)
#define SM_WH 0                               // elems
#define SM_WL (WJ_ * WSTR)                    // 33024
#define SM_HH (2 * WJ_ * WSTR)                // 66048
#define SM_HL (SM_HH + 8 * WB_ * HSTR)       // + 17408
#define SM_ELEMS (SM_HL + 8 * WB_ * HSTR)    // 100864 bf16 elems
#define RED_OFF  (SM_ELEMS * 2)              // byte offset of fp32 red buffer
#define REDSTR   34                           // floats per red row
#define RNN_SMEM (RED_OFF + 8 * WB_ * REDSTR * 4)  // 201728 + 17408 = 219136 B

__global__ __launch_bounds__(256, 1) void rnn_kernel(
    const float* __restrict__ Whh,
    const float* __restrict__ bhh,
    float* __restrict__ out)                   // d_out: (S,B,H) then h_final
{
    extern __shared__ __nv_bfloat16 smr[];
    __nv_bfloat16* Wh = smr + SM_WH;
    __nv_bfloat16* Wl = smr + SM_WL;
    __nv_bfloat16* Hh = smr + SM_HH;           // [8 warps][16][HSTR]
    __nv_bfloat16* Hl = smr + SM_HL;
    float* red = (float*)((char*)smr + RED_OFF);   // [8][16][REDSTR]

    const uint32_t wh_a = smem_u32(Wh);
    const uint32_t wl_a = smem_u32(Wl);
    const uint32_t hh_a = smem_u32(Hh);
    const uint32_t hl_a = smem_u32(Hl);

    const int t    = threadIdx.x;
    const int lane = t & 31;
    const int w    = t >> 5;                   // warp id = k-slice
    const int cta  = blockIdx.x;
    const int jt   = cta >> 2;                 // 0..31 (32 j cols)
    const int bt   = cta & 3;                  // 0..3  (16 b rows)
    const int j0   = jt * WJ_;
    const int bg0  = bt * WB_;

    // ldmatrix lane address components
    const int a_row = lane & 15;
    const int a_kof = ((lane >> 4) & 1) * 8;
    const int b_row = (lane & 7) + ((lane >> 4) & 1) * 8;
    const int b_kof = ((lane >> 3) & 1) * 8;
    const uint32_t hh_w = hh_a + (uint32_t)(w * WB_ * HSTR) * 2;
    const uint32_t hl_w = hl_a + (uint32_t)(w * WB_ * HSTR) * 2;

    // reducer constants: thread -> (b = t>>4, col pair = 2*(t&15))
    const int rb   = t >> 4;                   // 0..15
    const int rcol = (t & 15) * 2;             // 0..30
    const size_t oidx = ((size_t)(bg0 + rb) << 10) + j0 + rcol;
    const float bh0 = bhh[j0 + rcol];
    const float bh1 = bhh[j0 + rcol + 1];

    // ---- one-time: split W_hh tile (32 j x 1024 k) into SMEM hi/lo ----
#pragma unroll
    for (int i = 0; i < 32; i++) {
        const int f   = t + 256 * i;           // 0..8191 float4 slots
        const int row = f >> 8;                // 0..31 (j-local)
        const int k4  = (f & 255) * 4;         // 0..1020
        const float4 v = *(const float4*)(Whh + (size_t)(j0 + row) * H_ + k4);
        uint2 h, l;
        cvt_split4(v, h, l);
        *(uint2*)(Wh + row * WSTR + k4) = h;
        *(uint2*)(Wl + row * WSTR + k4) = l;
    }
    __syncthreads();

    for (int s = 0; s < S_; s++) {
        // ---- prefetch xi(s) block (independent of gate) ----
        const float2 xi2 = *(const float2*)(g_xi + (size_t)s * BH_ + oidx);

        // ---- warp-level gate + private stage of h(s-1) k-slice ----
        if (s == 0) {
#pragma unroll
            for (int i = 0; i < 8; i++) {
                const int f   = lane + 32 * i;   // 0..255
                const int row = f >> 4;
                const int k8  = (f & 15) * 8;
                *(uint4*)(Hh + w * WB_ * HSTR + row * HSTR + k8) = make_uint4(0, 0, 0, 0);
                *(uint4*)(Hl + w * WB_ * HSTR + row * HSTR + k8) = make_uint4(0, 0, 0, 0);
            }
            __syncwarp();
        } else {
            const unsigned tgt = 32u * (unsigned)s;
            while (*(volatile unsigned*)&g_hflag[bt] < tgt) { }
            __threadfence();
            __syncwarp();
            const __nv_bfloat16* shi = g_hh[(s + 1) & 1][0];
            const __nv_bfloat16* slo = g_hh[(s + 1) & 1][1];
#pragma unroll
            for (int i = 0; i < 8; i++) {
                const int f   = lane + 32 * i;   // 0..255 uint4 slots
                const int row = f >> 4;          // 0..15 (b-local)
                const int k8  = (f & 15) * 8;    // 0..120
                const size_t gsrc = ((size_t)(bg0 + row) << 10) + w * 128 + k8;
                *(uint4*)(Hh + w * WB_ * HSTR + row * HSTR + k8) = *(const uint4*)(shi + gsrc);
                *(uint4*)(Hl + w * WB_ * HSTR + row * HSTR + k8) = *(const uint4*)(slo + gsrc);
            }
            __syncwarp();
        }

        // ---- m16 n32 k128 x 3-term split HMMA (warp-private k-slice) ----
        float acc[4][4];
#pragma unroll
        for (int ni = 0; ni < 4; ni++)
#pragma unroll
            for (int q = 0; q < 4; q++) acc[ni][q] = 0.f;

#pragma unroll
        for (int kk = 0; kk < 128; kk += 16) {
            const int wk = w * 128 + kk;       // global k for W addressing
            uint32_t ah0, ah1, ah2, ah3, al0, al1, al2, al3;
            {
                const uint32_t off = (uint32_t)((a_row * HSTR + kk + a_kof) * 2);
                LDMX4(ah0, ah1, ah2, ah3, hh_w + off);
                LDMX4(al0, al1, al2, al3, hl_w + off);
            }
            uint32_t bh[8], bl[8];
#pragma unroll
            for (int p = 0; p < 2; p++) {
                const uint32_t off = (uint32_t)(((p * 16 + b_row) * WSTR + wk + b_kof) * 2);
                LDMX4(bh[p*4+0], bh[p*4+1], bh[p*4+2], bh[p*4+3], wh_a + off);
                LDMX4(bl[p*4+0], bl[p*4+1], bl[p*4+2], bl[p*4+3], wl_a + off);
            }
#pragma unroll
            for (int ni = 0; ni < 4; ni++) {
                MMA_BF16(acc[ni], ah0, ah1, ah2, ah3, bh[ni*2+0], bh[ni*2+1]);
                MMA_BF16(acc[ni], ah0, ah1, ah2, ah3, bl[ni*2+0], bl[ni*2+1]);
                MMA_BF16(acc[ni], al0, al1, al2, al3, bh[ni*2+0], bh[ni*2+1]);
            }
        }

        // ---- deposit warp partial (16x32) in SMEM ----
        {
            const int gr = lane >> 2;
            const int gc = (lane & 3) * 2;
            float* rw = red + w * WB_ * REDSTR;
#pragma unroll
            for (int ni = 0; ni < 4; ni++) {
                float2 v0, v1;
                v0.x = acc[ni][0]; v0.y = acc[ni][1];
                v1.x = acc[ni][2]; v1.y = acc[ni][3];
                *(float2*)&rw[gr * REDSTR + ni * 8 + gc]       = v0;
                *(float2*)&rw[(gr + 8) * REDSTR + ni * 8 + gc] = v1;
            }
        }
        __syncthreads();

        // ---- block reduce over 8 warps + xi + bias -> tanh -> h ----
        {
            float v0 = xi2.x + bh0;
            float v1 = xi2.y + bh1;
#pragma unroll
            for (int q = 0; q < 8; q++) {
                const float2 p = *(const float2*)&red[(q * WB_ + rb) * REDSTR + rcol];
                v0 += p.x; v1 += p.y;
            }
            const float h0 = tanhf(v0);
            const float h1 = tanhf(v1);
            float2 ho; ho.x = h0; ho.y = h1;
            *(float2*)(out + (size_t)s * BH_ + oidx) = ho;
            __nv_bfloat162 hb;
            hb.x = __float2bfloat16_rn(h0);
            hb.y = __float2bfloat16_rn(h1);
            *(__nv_bfloat162*)(g_hh[s & 1][0] + oidx) = hb;
            __nv_bfloat162 lb;
            lb.x = __float2bfloat16_rn(h0 - __bfloat162float(hb.x));
            lb.y = __float2bfloat16_rn(h1 - __bfloat162float(hb.y));
            *(__nv_bfloat162*)(g_hh[s & 1][1] + oidx) = lb;
            if (s == S_ - 1)
                *(float2*)(out + (size_t)S_ * BH_ + oidx) = ho;
        }

        // ---- signal h block ready (also recycles red buffer safely) ----
        __threadfence();
        __syncthreads();
        if (t == 0) atomicAdd(&g_hflag[bt], 1u);
    }
}

// =========================================================================
extern "C" void kernel_launch(void* const* d_in, const int* in_sizes, int n_in,
                              void* d_out, int out_size)
{
    (void)in_sizes; (void)n_in; (void)out_size;
    const float* x   = (const float*)d_in[0];
    const float* Wih = (const float*)d_in[1];
    const float* bih = (const float*)d_in[2];
    const float* Whh = (const float*)d_in[3];
    const float* bhh = (const float*)d_in[4];
    float* out = (float*)d_out;

    cudaFuncSetAttribute(rnn_kernel,  cudaFuncAttributeMaxDynamicSharedMemorySize, RNN_SMEM);
    cudaFuncSetAttribute(gemm_xi_mma, cudaFuncAttributeMaxDynamicSharedMemorySize, GEMM_SMEM);

    init_flags_kernel<<<1, 32>>>();
    split_x_kernel<<<R_, 256>>>(x);
    split_w_kernel<<<H_, 256>>>(Wih);
    gemm_xi_mma<<<dim3(8, 256, 1), 256, GEMM_SMEM>>>(bih);
    rnn_kernel<<<NCTA, 256, RNN_SMEM>>>(Whh, bhh, out);
}